// round 13
// baseline (speedup 1.0000x reference)
#include <cuda_runtime.h>
#include <cuda_bf16.h>
#include <cstdint>

#define BH 64
#define SEQ 8192
#define D 64
#define SPLITS 16
#define RPS (SEQ / SPLITS)      // 512
#define K1CH 32
#define K1NCH (RPS / K1CH)      // 16
#define PART_STRIDE (D * D + D)

__device__ float g_part[BH * SPLITS * PART_STRIDE];
__device__ float g_ctx[BH * D * D];

__device__ __forceinline__ uint32_t tf32r(float x) {
    uint32_t r;
    asm("cvt.rna.tf32.f32 %0, %1;" : "=r"(r) : "f"(x));
    return r;
}
__device__ __forceinline__ void mma_tf32(float* c, const uint32_t* a,
                                         uint32_t b0, uint32_t b1) {
    asm volatile(
        "mma.sync.aligned.m16n8k8.row.col.f32.tf32.tf32.f32 "
        "{%0,%1,%2,%3}, {%4,%5,%6,%7}, {%8,%9}, {%0,%1,%2,%3};"
        : "+f"(c[0]), "+f"(c[1]), "+f"(c[2]), "+f"(c[3])
        : "r"(a[0]), "r"(a[1]), "r"(a[2]), "r"(a[3]), "r"(b0), "r"(b1));
}
__device__ __forceinline__ uint32_t smem_u32(const void* p) {
    uint32_t a;
    asm("{ .reg .u64 t; cvta.to.shared.u64 t, %1; cvt.u32.u64 %0, t; }"
        : "=r"(a) : "l"(p));
    return a;
}
__device__ __forceinline__ void cpa16(uint32_t dst, const void* src) {
    asm volatile("cp.async.cg.shared.global [%0], [%1], 16;"
                 :: "r"(dst), "l"(src));
}
#define CPA_COMMIT() asm volatile("cp.async.commit_group;" ::: "memory")
#define CPA_WAIT(n) asm volatile("cp.async.wait_group %0;" :: "n"(n) : "memory")

// ============== Kernel 1: partial context  exp(K)^T @ V =====================
// grid (BH, SPLITS), 128 threads = 4 warps (2x2, warp tile M32xN32).
// cp.async streams RAW k,v into depth-2 rings (stride 72 words ->
// frag addr mod 32 = 8*t4+g+const, conflict-free). exp+tf32 in-register
// at fragment time; z-sums accumulated from A fragments.
#define KW 72
#define KCHW (K1CH * KW)   // words per buffer
__global__ void __launch_bounds__(128) ctx_partial_kernel(
    const float* __restrict__ k, const float* __restrict__ v) {
    __shared__ __align__(16) float kbuf[2][KCHW];  // 18.4 KB
    __shared__ __align__(16) float vbuf[2][KCHW];  // 18.4 KB

    const int head = blockIdx.x, split = blockIdx.y;
    const float* kb = k + (size_t)head * SEQ * D + (size_t)split * RPS * D;
    const float* vb = v + (size_t)head * SEQ * D + (size_t)split * RPS * D;

    const int tid = threadIdx.x;
    const int lane = tid & 31;
    const int wq = tid >> 5;
    const int g = lane >> 2, t4 = lane & 3;
    const int wm = wq & 1, wn = wq >> 1;
    const int sr = tid >> 4;
    const int c4 = (tid & 15) * 4;

    const uint32_t uK[2] = {smem_u32(kbuf[0]), smem_u32(kbuf[1])};
    const uint32_t uV[2] = {smem_u32(vbuf[0]), smem_u32(vbuf[1])};

    float acc[2][4][4];
#pragma unroll
    for (int i = 0; i < 2; i++)
#pragma unroll
        for (int j = 0; j < 4; j++)
#pragma unroll
            for (int l = 0; l < 4; l++) acc[i][j][l] = 0.0f;
    float zacc[2][2] = {{0.0f, 0.0f}, {0.0f, 0.0f}};

    // prologue: chunk 0 -> buf 0
#pragma unroll
    for (int s = 0; s < 4; s++) {
        const int r = s * 8 + sr;
        cpa16(uK[0] + (r * KW + c4) * 4, &kb[(size_t)r * D + c4]);
        cpa16(uV[0] + (r * KW + c4) * 4, &vb[(size_t)r * D + c4]);
    }
    CPA_COMMIT();

    for (int c = 0; c < K1NCH; c++) {
        const int p = c & 1;
        if (c + 1 < K1NCH) {
#pragma unroll
            for (int s = 0; s < 4; s++) {
                const int r = s * 8 + sr;
                const size_t go = (size_t)((c + 1) * K1CH + r) * D + c4;
                cpa16(uK[p ^ 1] + (r * KW + c4) * 4, &kb[go]);
                cpa16(uV[p ^ 1] + (r * KW + c4) * 4, &vb[go]);
            }
            CPA_COMMIT();
            CPA_WAIT(1);
        } else {
            CPA_WAIT(0);
        }
        __syncthreads();   // chunk c landed, visible to all

        const float* kp_ = kbuf[p];
        const float* vp_ = vbuf[p];
#pragma unroll
        for (int ks = 0; ks < 4; ks++) {
            const int n0 = ks * 8;
            const int ra = (n0 + t4) * KW, rb = (n0 + 4 + t4) * KW;
            uint32_t A[2][4];
#pragma unroll
            for (int mt = 0; mt < 2; mt++) {
                const int dd = wm * 32 + mt * 16 + g;
                const float x0 = kp_[ra + dd];
                const float x1 = kp_[ra + dd + 8];
                const float x2 = kp_[rb + dd];
                const float x3 = kp_[rb + dd + 8];
                A[mt][0] = tf32r(__expf(x0));
                A[mt][1] = tf32r(__expf(x1));
                A[mt][2] = tf32r(__expf(x2));
                A[mt][3] = tf32r(__expf(x3));
                zacc[mt][0] += __uint_as_float(A[mt][0]) + __uint_as_float(A[mt][2]);
                zacc[mt][1] += __uint_as_float(A[mt][1]) + __uint_as_float(A[mt][3]);
            }
#pragma unroll
            for (int nt = 0; nt < 4; nt++) {
                const int ee = wn * 32 + nt * 8 + g;
                uint32_t b0 = tf32r(vp_[ra + ee]);
                uint32_t b1 = tf32r(vp_[rb + ee]);
                mma_tf32(acc[0][nt], A[0], b0, b1);
                mma_tf32(acc[1][nt], A[1], b0, b1);
            }
        }
        __syncthreads();   // all reads of buf p done before next cpa hits it
    }

    float* np = g_part + (size_t)(head * SPLITS + split) * PART_STRIDE;
#pragma unroll
    for (int mt = 0; mt < 2; mt++) {
        const int d0 = wm * 32 + mt * 16 + g;
#pragma unroll
        for (int nt = 0; nt < 4; nt++) {
            const int ee = wn * 32 + nt * 8 + 2 * t4;
            *(float2*)&np[d0 * D + ee] =
                make_float2(acc[mt][nt][0], acc[mt][nt][1]);
            *(float2*)&np[(d0 + 8) * D + ee] =
                make_float2(acc[mt][nt][2], acc[mt][nt][3]);
        }
    }
    // z: complete rows over t4 lanes; wn==0 publishes (wn pairs duplicate)
#pragma unroll
    for (int mt = 0; mt < 2; mt++)
#pragma unroll
        for (int h = 0; h < 2; h++) {
            float vz = zacc[mt][h];
            vz += __shfl_xor_sync(0xffffffffu, vz, 1);
            vz += __shfl_xor_sync(0xffffffffu, vz, 2);
            zacc[mt][h] = vz;
        }
    if (wn == 0 && t4 == 0) {
#pragma unroll
        for (int mt = 0; mt < 2; mt++) {
            const int d0 = wm * 32 + mt * 16 + g;
            np[D * D + d0] = zacc[mt][0];
            np[D * D + d0 + 8] = zacc[mt][1];
        }
    }
}

// ============== Kernel 2: reduce splits + normalize -> g_ctx ================
__global__ void __launch_bounds__(256) reduce_ctx_kernel() {
    const int head = blockIdx.x;
    const int tid = threadIdx.x;
    __shared__ float zs[D];
    const float* pb = g_part + (size_t)head * SPLITS * PART_STRIDE;

    if (tid < D) {
        float s = 0.0f;
#pragma unroll
        for (int sp = 0; sp < SPLITS; sp++) s += pb[sp * PART_STRIDE + D * D + tid];
        zs[tid] = 1.0f / s;
    }
    __syncthreads();

    const int i0 = blockIdx.y * 1024;
    for (int i = i0 + tid; i < i0 + 1024; i += 256) {
        float s = 0.0f;
#pragma unroll
        for (int sp = 0; sp < SPLITS; sp++) s += pb[sp * PART_STRIDE + i];
        g_ctx[head * D * D + i] = s * zs[i >> 6];
    }
}

// ============== Kernel 3: out = (softmax_ch(q)/8) @ ctx  (frozen, R12) ======
#define QS_W 68
#define QS_WORDS (64 * QS_W)                  // 4352
#define K3_SMEM ((2 * QS_WORDS + 64 * 72 + 64) * 4)   // ~53.5 KB

__global__ void __launch_bounds__(128) out_kernel(
    const float* __restrict__ q, float* __restrict__ out) {
    extern __shared__ uint32_t sm3[];
    uint32_t* qs0 = sm3;
    uint32_t* qs1 = sm3 + QS_WORDS;
    uint32_t* ctxs = sm3 + 2 * QS_WORDS;      // 64*72
    float* ssum = (float*)(sm3 + 2 * QS_WORDS + 64 * 72);

    const int tid = threadIdx.x;
    const int lane = tid & 31;
    const int wq = tid >> 5;
    const int g = lane >> 2, t4 = lane & 3;
    const int wm = wq & 1, wn = wq >> 1;
    const int sr = tid >> 4;
    const int c4 = (tid & 15) * 4;
    const int head = blockIdx.x;

    const uint32_t uQs0 = smem_u32(qs0), uQs1 = smem_u32(qs1);

    const float* gc = g_ctx + (size_t)head * D * D;
    for (int i = tid; i < 64 * 16; i += 128) {
        const int d = i >> 4, cg4 = (i & 15) * 4;
        float4 cv = *(const float4*)&gc[d * D + cg4];
        uint4 cu;
        cu.x = tf32r(cv.x); cu.y = tf32r(cv.y);
        cu.z = tf32r(cv.z); cu.w = tf32r(cv.w);
        *(uint4*)&ctxs[d * 72 + cg4] = cu;
    }

    const float* qh = q + (size_t)head * SEQ * D;
    const int tile0 = blockIdx.y * 8;

#pragma unroll
    for (int s = 0; s < 8; s++) {
        const int r = s * 8 + sr;
        cpa16(uQs0 + (r * QS_W + c4) * 4,
              &qh[(size_t)(tile0 * 64 + r) * D + c4]);
    }
    CPA_COMMIT();

    for (int t = 0; t < 8; t++) {
        const int p = t & 1;
        const int row0 = (tile0 + t) * 64;

        if (t + 1 < 8) {
            const uint32_t uDst = p ? uQs0 : uQs1;
#pragma unroll
            for (int s = 0; s < 8; s++) {
                const int r = s * 8 + sr;
                cpa16(uDst + (r * QS_W + c4) * 4,
                      &qh[(size_t)(row0 + 64 + r) * D + c4]);
            }
            CPA_COMMIT();
            CPA_WAIT(1);
        } else {
            CPA_WAIT(0);
        }
        __syncthreads();

        const uint32_t* qsp = p ? qs1 : qs0;

        float acc[2][4][4];
#pragma unroll
        for (int i = 0; i < 2; i++)
#pragma unroll
            for (int j = 0; j < 4; j++)
#pragma unroll
                for (int l = 0; l < 4; l++) acc[i][j][l] = 0.0f;
        float asum[2][2] = {{0.0f, 0.0f}, {0.0f, 0.0f}};

#pragma unroll
        for (int ks = 0; ks < 8; ks++) {
            const int d0 = ks * 8;
            uint32_t A[2][4];
#pragma unroll
            for (int mt = 0; mt < 2; mt++) {
                const int rb = wm * 32 + mt * 16;
                const float x0 = __uint_as_float(qsp[(rb + g) * QS_W + d0 + t4]);
                const float x1 = __uint_as_float(qsp[(rb + 8 + g) * QS_W + d0 + t4]);
                const float x2 = __uint_as_float(qsp[(rb + g) * QS_W + d0 + 4 + t4]);
                const float x3 = __uint_as_float(qsp[(rb + 8 + g) * QS_W + d0 + 4 + t4]);
                A[mt][0] = tf32r(__expf(x0));
                A[mt][1] = tf32r(__expf(x1));
                A[mt][2] = tf32r(__expf(x2));
                A[mt][3] = tf32r(__expf(x3));
                asum[mt][0] += __uint_as_float(A[mt][0]) + __uint_as_float(A[mt][2]);
                asum[mt][1] += __uint_as_float(A[mt][1]) + __uint_as_float(A[mt][3]);
            }
            const int ra = (d0 + t4) * 72, rbb = (d0 + 4 + t4) * 72;
#pragma unroll
            for (int nt = 0; nt < 4; nt++) {
                const int ee = wn * 32 + nt * 8 + g;
                uint32_t b0 = ctxs[ra + ee];
                uint32_t b1 = ctxs[rbb + ee];
                mma_tf32(acc[0][nt], A[0], b0, b1);
                mma_tf32(acc[1][nt], A[1], b0, b1);
            }
        }

#pragma unroll
        for (int mt = 0; mt < 2; mt++)
#pragma unroll
            for (int h = 0; h < 2; h++) {
                float v = asum[mt][h];
                v += __shfl_xor_sync(0xffffffffu, v, 1);
                v += __shfl_xor_sync(0xffffffffu, v, 2);
                asum[mt][h] = v;
            }
        if (wn == 0 && t4 == 0) {
#pragma unroll
            for (int mt = 0; mt < 2; mt++) {
                const int rb = wm * 32 + mt * 16;
                ssum[rb + g] = 0.125f / asum[mt][0];
                ssum[rb + 8 + g] = 0.125f / asum[mt][1];
            }
        }
        __syncthreads();

        float* ob = out + (size_t)head * SEQ * D + (size_t)row0 * D;
#pragma unroll
        for (int mt = 0; mt < 2; mt++) {
            const int r0 = wm * 32 + mt * 16 + g;
            const float f0 = ssum[r0], f1 = ssum[r0 + 8];
#pragma unroll
            for (int nt = 0; nt < 4; nt++) {
                const int cc = wn * 32 + nt * 8 + 2 * t4;
                *(float2*)&ob[r0 * D + cc] =
                    make_float2(acc[mt][nt][0] * f0, acc[mt][nt][1] * f0);
                *(float2*)&ob[(r0 + 8) * D + cc] =
                    make_float2(acc[mt][nt][2] * f1, acc[mt][nt][3] * f1);
            }
        }
    }
}

// ================= launch =================
extern "C" void kernel_launch(void* const* d_in, const int* in_sizes, int n_in,
                              void* d_out, int out_size) {
    const float* q = (const float*)d_in[0];
    const float* k = (const float*)d_in[1];
    const float* v = (const float*)d_in[2];
    float* out = (float*)d_out;
    (void)in_sizes; (void)n_in; (void)out_size;

    static int attr_set = 0;
    if (!attr_set) {
        cudaFuncSetAttribute(out_kernel, cudaFuncAttributeMaxDynamicSharedMemorySize,
                             K3_SMEM);
        attr_set = 1;
    }

    ctx_partial_kernel<<<dim3(BH, SPLITS), 128>>>(k, v);
    reduce_ctx_kernel<<<dim3(BH, 4), 256>>>();
    out_kernel<<<dim3(BH, 16), 128, K3_SMEM>>>(q, out);
}